// round 5
// baseline (speedup 1.0000x reference)
#include <cuda_runtime.h>

// Problem constants
#define BATCH   2
#define SEQ     2048
#define DMODEL  1024
#define NHEAD   16
#define HDIM    64
#define MROWS   (BATCH * SEQ)     // 4096
#define QKVN    (3 * DMODEL)      // 3072

// Scratch (no cudaMalloc allowed): qkv activations + attention output
__device__ float g_qkv[MROWS * QKVN];     // [B*S, 3*D]  (~50 MB)
__device__ float g_val[MROWS * DMODEL];   // [B*S, D]    (~17 MB)

// ---------------------------------------------------------------------------
// SGEMM (NT): C[M,N] = A[M,K] * W[N,K]^T + bias[N]
// 128x128 tile, BK=16, 256 threads, 8x8 micro-tile (split 4+4 at stride 64)
// ---------------------------------------------------------------------------
#define BM 128
#define BN 128
#define BK 16

__global__ __launch_bounds__(256)
void sgemm_nt_bias(const float* __restrict__ A,
                   const float* __restrict__ W,
                   const float* __restrict__ bias,
                   float* __restrict__ C,
                   int M, int N, int K)
{
    __shared__ float As[BK][BM + 4];
    __shared__ float Bs[BK][BN + 4];

    const int tid = threadIdx.x;
    const int tx  = tid & 15;     // 0..15 (N dir)
    const int ty  = tid >> 4;     // 0..15 (M dir)
    const int bn  = blockIdx.x * BN;
    const int bm  = blockIdx.y * BM;

    // Tile-load mapping: 4 threads per row, each a float4 along K; 2 rows/thread
    const int lr = tid >> 2;          // 0..63
    const int lk = (tid & 3) << 2;    // 0,4,8,12

    float acc[8][8];
    #pragma unroll
    for (int i = 0; i < 8; i++)
        #pragma unroll
        for (int j = 0; j < 8; j++) acc[i][j] = 0.0f;

    for (int k0 = 0; k0 < K; k0 += BK) {
        #pragma unroll
        for (int h = 0; h < 2; h++) {
            const int row = lr + h * 64;
            float4 va = *(const float4*)(A + (size_t)(bm + row) * K + k0 + lk);
            As[lk + 0][row] = va.x; As[lk + 1][row] = va.y;
            As[lk + 2][row] = va.z; As[lk + 3][row] = va.w;
            float4 vb = *(const float4*)(W + (size_t)(bn + row) * K + k0 + lk);
            Bs[lk + 0][row] = vb.x; Bs[lk + 1][row] = vb.y;
            Bs[lk + 2][row] = vb.z; Bs[lk + 3][row] = vb.w;
        }
        __syncthreads();

        #pragma unroll
        for (int k = 0; k < BK; k++) {
            float a[8], b[8];
            #pragma unroll
            for (int i = 0; i < 4; i++) {
                a[i]     = As[k][ty * 4 + i];
                a[4 + i] = As[k][64 + ty * 4 + i];
            }
            #pragma unroll
            for (int j = 0; j < 4; j++) {
                b[j]     = Bs[k][tx * 4 + j];
                b[4 + j] = Bs[k][64 + tx * 4 + j];
            }
            #pragma unroll
            for (int i = 0; i < 8; i++)
                #pragma unroll
                for (int j = 0; j < 8; j++)
                    acc[i][j] += a[i] * b[j];
        }
        __syncthreads();
    }

    // Epilogue: bias + float4 stores (cols tx*4.. and 64+tx*4.. are contiguous)
    const int c0 = bn + tx * 4;
    const int c1 = bn + 64 + tx * 4;
    float4 bv0, bv1;
    bv0 = *(const float4*)(bias + c0);
    bv1 = *(const float4*)(bias + c1);

    #pragma unroll
    for (int i = 0; i < 8; i++) {
        const int row = bm + ((i < 4) ? (ty * 4 + i) : (64 + ty * 4 + (i - 4)));
        float4 r0, r1;
        r0.x = acc[i][0] + bv0.x; r0.y = acc[i][1] + bv0.y;
        r0.z = acc[i][2] + bv0.z; r0.w = acc[i][3] + bv0.w;
        r1.x = acc[i][4] + bv1.x; r1.y = acc[i][5] + bv1.y;
        r1.z = acc[i][6] + bv1.z; r1.w = acc[i][7] + bv1.w;
        *(float4*)(C + (size_t)row * N + c0) = r0;
        *(float4*)(C + (size_t)row * N + c1) = r1;
    }
}

// ---------------------------------------------------------------------------
// Flash attention (fp32, online softmax).
// One CTA = 128 query rows of one (b,h); one thread = one query row.
// q[64] and o[64] register-resident; K/V tiles of 32 keys staged in smem.
// ---------------------------------------------------------------------------
#define BQ  128
#define BKT 32

__global__ __launch_bounds__(128)
void flash_attn_kernel()
{
    __shared__ float4 Ks[BKT][HDIM / 4];   // 32 x 16 float4 = 8 KB
    __shared__ float4 Vs[BKT][HDIM / 4];

    const int tid = threadIdx.x;
    const int bh  = blockIdx.y;
    const int b   = bh >> 4;
    const int h   = bh & 15;
    const int srow = blockIdx.x * BQ + tid;

    // Q row -> registers
    const float4* qv = (const float4*)(g_qkv + (size_t)(b * SEQ + srow) * QKVN + h * 3 * HDIM);
    float q[HDIM];
    #pragma unroll
    for (int i = 0; i < 16; i++) {
        float4 t = qv[i];
        q[4*i] = t.x; q[4*i+1] = t.y; q[4*i+2] = t.z; q[4*i+3] = t.w;
    }

    float o[HDIM];
    #pragma unroll
    for (int i = 0; i < HDIM; i++) o[i] = 0.0f;
    float mmax = -1e30f, l = 0.0f;
    const float rscale = 0.125f;   // 1/sqrt(64)

    const int lrow = tid >> 2;            // 0..31 (key row this thread loads)
    const int lc4  = (tid & 3) * 4;       // float4 index 0,4,8,12

    for (int kt = 0; kt < SEQ; kt += BKT) {
        __syncthreads();   // previous tile's reads complete before overwrite
        {
            const float4* kbase = (const float4*)(g_qkv +
                (size_t)(b * SEQ + kt + lrow) * QKVN + h * 3 * HDIM + HDIM);
            const float4* vbase = kbase + (HDIM / 4);
            #pragma unroll
            for (int i = 0; i < 4; i++) {
                Ks[lrow][lc4 + i] = kbase[lc4 + i];
                Vs[lrow][lc4 + i] = vbase[lc4 + i];
            }
        }
        __syncthreads();

        // scores for 32 keys (fully unrolled so sc[] stays in registers)
        float sc[BKT];
        float mnew = mmax;
        #pragma unroll
        for (int j = 0; j < BKT; j++) {
            float s0 = 0.f, s1 = 0.f, s2 = 0.f, s3 = 0.f;
            #pragma unroll
            for (int i = 0; i < 16; i++) {
                float4 kv = Ks[j][i];
                s0 += q[4*i]   * kv.x;
                s1 += q[4*i+1] * kv.y;
                s2 += q[4*i+2] * kv.z;
                s3 += q[4*i+3] * kv.w;
            }
            float s = ((s0 + s1) + (s2 + s3)) * rscale;
            sc[j] = s;
            mnew = fmaxf(mnew, s);
        }

        // online softmax rescale
        const float corr = __expf(mmax - mnew);
        l *= corr;
        #pragma unroll
        for (int i = 0; i < HDIM; i++) o[i] *= corr;

        #pragma unroll
        for (int j = 0; j < BKT; j++) {
            const float p = __expf(sc[j] - mnew);
            l += p;
            #pragma unroll
            for (int i = 0; i < 16; i++) {
                float4 v = Vs[j][i];
                o[4*i]   += p * v.x;
                o[4*i+1] += p * v.y;
                o[4*i+2] += p * v.z;
                o[4*i+3] += p * v.w;
            }
        }
        mmax = mnew;
    }

    const float inv = 1.0f / l;
    float4* optr = (float4*)(g_val + (size_t)(b * SEQ + srow) * DMODEL + h * HDIM);
    #pragma unroll
    for (int i = 0; i < 16; i++) {
        float4 t;
        t.x = o[4*i]   * inv; t.y = o[4*i+1] * inv;
        t.z = o[4*i+2] * inv; t.w = o[4*i+3] * inv;
        optr[i] = t;
    }
}

// ---------------------------------------------------------------------------
// Launch: QKV GEMM -> flash attention -> output GEMM (default stream, graph-safe)
// ---------------------------------------------------------------------------
extern "C" void kernel_launch(void* const* d_in, const int* in_sizes, int n_in,
                              void* d_out, int out_size)
{
    const float* x     = (const float*)d_in[0];   // [2,2048,1024]
    const float* w_qkv = (const float*)d_in[1];   // [3072,1024]
    const float* b_qkv = (const float*)d_in[2];   // [3072]
    const float* w_fc  = (const float*)d_in[3];   // [1024,1024]
    const float* b_fc  = (const float*)d_in[4];   // [1024]
    float* out = (float*)d_out;                   // [2,2048,1024]

    float* qkv_d = nullptr;
    float* val_d = nullptr;
    cudaGetSymbolAddress((void**)&qkv_d, g_qkv);
    cudaGetSymbolAddress((void**)&val_d, g_val);

    // 1) QKV projection: [4096,1024] x [3072,1024]^T + b -> [4096,3072]
    sgemm_nt_bias<<<dim3(QKVN / BN, MROWS / BM), 256>>>(
        x, w_qkv, b_qkv, qkv_d, MROWS, QKVN, DMODEL);

    // 2) Flash attention over all (b,h): writes g_val [4096,1024]
    flash_attn_kernel<<<dim3(SEQ / BQ, BATCH * NHEAD), 128>>>();

    // 3) Output projection: [4096,1024] x [1024,1024]^T + b -> out
    sgemm_nt_bias<<<dim3(DMODEL / BN, MROWS / BM), 256>>>(
        val_d, w_fc, b_fc, out, MROWS, DMODEL, DMODEL);
}

// round 9
// speedup vs baseline: 1.0204x; 1.0204x over previous
#include <cuda_runtime.h>

// Problem constants
#define BATCH   2
#define SEQ     2048
#define DMODEL  1024
#define NHEAD   16
#define HDIM    64
#define MROWS   (BATCH * SEQ)     // 4096
#define QKVN    (3 * DMODEL)      // 3072

typedef unsigned long long u64;

// ---- packed fp32x2 primitives (sm_100+/sm_103a) --------------------------
__device__ __forceinline__ u64 ffma2(u64 a, u64 b, u64 c) {
    u64 d;
    asm("fma.rn.f32x2 %0, %1, %2, %3;" : "=l"(d) : "l"(a), "l"(b), "l"(c));
    return d;
}
__device__ __forceinline__ u64 fmul2(u64 a, u64 b) {
    u64 d;
    asm("mul.rn.f32x2 %0, %1, %2;" : "=l"(d) : "l"(a), "l"(b));
    return d;
}
__device__ __forceinline__ u64 pack2(float lo, float hi) {
    u64 d;
    asm("mov.b64 %0, {%1, %2};" : "=l"(d) : "f"(lo), "f"(hi));
    return d;
}
__device__ __forceinline__ float2 unpack2(u64 v) {
    float2 r;
    asm("mov.b64 {%0, %1}, %2;" : "=f"(r.x), "=f"(r.y) : "l"(v));
    return r;
}

// Scratch (no cudaMalloc allowed): qkv activations + attention output
__device__ float g_qkv[MROWS * QKVN];     // [B*S, 3*D]
__device__ float g_val[MROWS * DMODEL];   // [B*S, D]

// ---------------------------------------------------------------------------
// SGEMM (NT): C[M,N] = A[M,K] * W[N,K]^T + bias[N]
// 128x128 tile, BK=16, 256 threads, 8x8 micro-tile via packed f32x2 FMA.
// ---------------------------------------------------------------------------
#define BM 128
#define BN 128
#define BK 16

__global__ __launch_bounds__(256)
void sgemm_nt_bias(const float* __restrict__ A,
                   const float* __restrict__ W,
                   const float* __restrict__ bias,
                   float* __restrict__ C,
                   int M, int N, int K)
{
    __shared__ __align__(16) float As[BK][BM + 4];
    __shared__ __align__(16) float Bs[BK][BN + 4];

    const int tid = threadIdx.x;
    const int tx  = tid & 15;     // 0..15 (N dir)
    const int ty  = tid >> 4;     // 0..15 (M dir)
    const int bn  = blockIdx.x * BN;
    const int bm  = blockIdx.y * BM;

    // Tile-load mapping: 4 threads per row, each a float4 along K; 2 rows/thread
    const int lr = tid >> 2;          // 0..63
    const int lk = (tid & 3) << 2;    // 0,4,8,12

    // acc2[i][j] holds output pair (row i, cols 2j..2j+1 of the 8-col strip)
    u64 acc2[8][4];
    #pragma unroll
    for (int i = 0; i < 8; i++)
        #pragma unroll
        for (int j = 0; j < 4; j++) acc2[i][j] = 0ULL;

    for (int k0 = 0; k0 < K; k0 += BK) {
        #pragma unroll
        for (int h = 0; h < 2; h++) {
            const int row = lr + h * 64;
            float4 va = *(const float4*)(A + (size_t)(bm + row) * K + k0 + lk);
            As[lk + 0][row] = va.x; As[lk + 1][row] = va.y;
            As[lk + 2][row] = va.z; As[lk + 3][row] = va.w;
            float4 vb = *(const float4*)(W + (size_t)(bn + row) * K + k0 + lk);
            Bs[lk + 0][row] = vb.x; Bs[lk + 1][row] = vb.y;
            Bs[lk + 2][row] = vb.z; Bs[lk + 3][row] = vb.w;
        }
        __syncthreads();

        #pragma unroll
        for (int k = 0; k < BK; k++) {
            float4 a0 = *(const float4*)&As[k][ty * 4];
            float4 a1 = *(const float4*)&As[k][64 + ty * 4];
            ulonglong2 b0 = *(const ulonglong2*)&Bs[k][tx * 4];
            ulonglong2 b1 = *(const ulonglong2*)&Bs[k][64 + tx * 4];

            u64 aa[8];
            aa[0] = pack2(a0.x, a0.x); aa[1] = pack2(a0.y, a0.y);
            aa[2] = pack2(a0.z, a0.z); aa[3] = pack2(a0.w, a0.w);
            aa[4] = pack2(a1.x, a1.x); aa[5] = pack2(a1.y, a1.y);
            aa[6] = pack2(a1.z, a1.z); aa[7] = pack2(a1.w, a1.w);
            u64 bb[4] = { b0.x, b0.y, b1.x, b1.y };

            #pragma unroll
            for (int i = 0; i < 8; i++)
                #pragma unroll
                for (int j = 0; j < 4; j++)
                    acc2[i][j] = ffma2(aa[i], bb[j], acc2[i][j]);
        }
        __syncthreads();
    }

    // Epilogue: bias + float4 stores
    const int c0 = bn + tx * 4;
    const int c1 = bn + 64 + tx * 4;
    float4 bv0 = *(const float4*)(bias + c0);
    float4 bv1 = *(const float4*)(bias + c1);

    #pragma unroll
    for (int i = 0; i < 8; i++) {
        const int row = bm + ((i < 4) ? (ty * 4 + i) : (64 + ty * 4 + (i - 4)));
        float2 p0 = unpack2(acc2[i][0]);
        float2 p1 = unpack2(acc2[i][1]);
        float2 p2 = unpack2(acc2[i][2]);
        float2 p3 = unpack2(acc2[i][3]);
        float4 r0, r1;
        r0.x = p0.x + bv0.x; r0.y = p0.y + bv0.y;
        r0.z = p1.x + bv0.z; r0.w = p1.y + bv0.w;
        r1.x = p2.x + bv1.x; r1.y = p2.y + bv1.y;
        r1.z = p3.x + bv1.z; r1.w = p3.y + bv1.w;
        *(float4*)(C + (size_t)row * N + c0) = r0;
        *(float4*)(C + (size_t)row * N + c1) = r1;
    }
}

// ---------------------------------------------------------------------------
// Flash attention (fp32, online softmax), packed f32x2 math.
// 2 threads per query row (headdim split 32/32, joined by shfl.xor 1).
// CTA = 128 threads = 64 query rows of one (b,h); K/V tiles of 32 keys in smem.
// Smem key row = [half0: 36 floats (32+4 pad)][half1: 36 floats] -> the two
// half-addresses per warp land on different banks (delta = 144B = bank+4).
// ---------------------------------------------------------------------------
#define BQ2 64
#define BKT 32
#define KROW 72   // padded floats per key row

__global__ __launch_bounds__(128)
void flash_attn_kernel()
{
    __shared__ __align__(16) float Ks[BKT * KROW];   // 9216 B
    __shared__ __align__(16) float Vs[BKT * KROW];   // 9216 B

    const int tid  = threadIdx.x;
    const int half = tid & 1;          // which 32-dim half of the row
    const int rloc = tid >> 1;         // 0..63 query row within CTA
    const int bh   = blockIdx.y;
    const int b    = bh >> 4;
    const int h    = bh & 15;
    const int srow = blockIdx.x * BQ2 + rloc;

    // Q half-row -> 16 packed f32x2 registers
    const ulonglong2* qv = (const ulonglong2*)(g_qkv +
        (size_t)(b * SEQ + srow) * QKVN + h * 3 * HDIM + half * 32);
    u64 q2[16];
    #pragma unroll
    for (int i = 0; i < 8; i++) {
        ulonglong2 t = qv[i];
        q2[2 * i] = t.x; q2[2 * i + 1] = t.y;
    }

    u64 o2[16];
    #pragma unroll
    for (int i = 0; i < 16; i++) o2[i] = 0ULL;
    float mmax = -1e30f, l = 0.0f;
    const float rscale = 0.125f;    // 1/sqrt(64)

    // tile loader mapping: 4 threads per key row, each 4 float4 (stride 4)
    const int lrow = tid >> 2;          // 0..31 key row
    const int lf4  = (tid & 3) * 4;     // float4 base: 0,4,8,12

    for (int kt = 0; kt < SEQ; kt += BKT) {
        __syncthreads();   // previous tile's reads done before overwrite
        {
            const float4* kg = (const float4*)(g_qkv +
                (size_t)(b * SEQ + kt + lrow) * QKVN + h * 3 * HDIM + HDIM);
            const float4* vg = kg + (HDIM / 4);
            #pragma unroll
            for (int i = 0; i < 4; i++) {
                const int c4  = lf4 + i;                          // 0..15
                const int dst = lrow * KROW + c4 * 4 + (c4 >= 8 ? 4 : 0);
                *(float4*)(Ks + dst) = kg[c4];
                *(float4*)(Vs + dst) = vg[c4];
            }
        }
        __syncthreads();

        // scores (this thread's 32-dim partial, joined with pair via shfl)
        float sc[BKT];
        float mnew = mmax;
        #pragma unroll
        for (int j = 0; j < BKT; j++) {
            const ulonglong2* kp = (const ulonglong2*)(Ks + j * KROW + half * 36);
            u64 sa = 0ULL, sb = 0ULL;
            #pragma unroll
            for (int i = 0; i < 8; i++) {
                ulonglong2 kv = kp[i];
                sa = ffma2(q2[2 * i],     kv.x, sa);
                sb = ffma2(q2[2 * i + 1], kv.y, sb);
            }
            float2 fa = unpack2(sa), fb = unpack2(sb);
            float sp = (fa.x + fa.y) + (fb.x + fb.y);
            sp += __shfl_xor_sync(0xffffffffu, sp, 1);   // add other half
            sp *= rscale;
            sc[j] = sp;
            mnew = fmaxf(mnew, sp);
        }

        // online softmax rescale
        const float corr = __expf(mmax - mnew);
        l *= corr;
        const u64 corr2 = pack2(corr, corr);
        #pragma unroll
        for (int i = 0; i < 16; i++) o2[i] = fmul2(o2[i], corr2);

        #pragma unroll
        for (int j = 0; j < BKT; j++) {
            const float p = __expf(sc[j] - mnew);
            l += p;
            const u64 p2 = pack2(p, p);
            const ulonglong2* vp = (const ulonglong2*)(Vs + j * KROW + half * 36);
            #pragma unroll
            for (int i = 0; i < 8; i++) {
                ulonglong2 vv = vp[i];
                o2[2 * i]     = ffma2(p2, vv.x, o2[2 * i]);
                o2[2 * i + 1] = ffma2(p2, vv.y, o2[2 * i + 1]);
            }
        }
        mmax = mnew;
    }

    const float inv = 1.0f / l;
    const u64 inv2 = pack2(inv, inv);
    ulonglong2* op = (ulonglong2*)(g_val +
        (size_t)(b * SEQ + srow) * DMODEL + h * HDIM + half * 32);
    #pragma unroll
    for (int i = 0; i < 8; i++) {
        ulonglong2 t;
        t.x = fmul2(o2[2 * i],     inv2);
        t.y = fmul2(o2[2 * i + 1], inv2);
        op[i] = t;
    }
}

// ---------------------------------------------------------------------------
// Launch: QKV GEMM -> flash attention -> output GEMM (default stream, graph-safe)
// ---------------------------------------------------------------------------
extern "C" void kernel_launch(void* const* d_in, const int* in_sizes, int n_in,
                              void* d_out, int out_size)
{
    const float* x     = (const float*)d_in[0];   // [2,2048,1024]
    const float* w_qkv = (const float*)d_in[1];   // [3072,1024]
    const float* b_qkv = (const float*)d_in[2];   // [3072]
    const float* w_fc  = (const float*)d_in[3];   // [1024,1024]
    const float* b_fc  = (const float*)d_in[4];   // [1024]
    float* out = (float*)d_out;                   // [2,2048,1024]

    float* qkv_d = nullptr;
    float* val_d = nullptr;
    cudaGetSymbolAddress((void**)&qkv_d, g_qkv);
    cudaGetSymbolAddress((void**)&val_d, g_val);

    // 1) QKV projection: [4096,1024] x [3072,1024]^T + b -> [4096,3072]
    sgemm_nt_bias<<<dim3(QKVN / BN, MROWS / BM), 256>>>(
        x, w_qkv, b_qkv, qkv_d, MROWS, QKVN, DMODEL);

    // 2) Flash attention over all (b,h): writes g_val [4096,1024]
    flash_attn_kernel<<<dim3(SEQ / BQ2, BATCH * NHEAD), 128>>>();

    // 3) Output projection: [4096,1024] x [1024,1024]^T + b -> out
    sgemm_nt_bias<<<dim3(DMODEL / BN, MROWS / BM), 256>>>(
        val_d, w_fc, b_fc, out, MROWS, DMODEL, DMODEL);
}

// round 13
// speedup vs baseline: 1.2190x; 1.1947x over previous
#include <cuda_runtime.h>
#include <cstdint>

// Problem constants
#define BATCH   2
#define SEQ     2048
#define DMODEL  1024
#define NHEAD   16
#define HDIM    64
#define MROWS   (BATCH * SEQ)     // 4096
#define QKVN    (3 * DMODEL)      // 3072

typedef unsigned long long u64;

// ---- packed fp32x2 primitives (used by flash attention) -------------------
__device__ __forceinline__ u64 ffma2(u64 a, u64 b, u64 c) {
    u64 d;
    asm("fma.rn.f32x2 %0, %1, %2, %3;" : "=l"(d) : "l"(a), "l"(b), "l"(c));
    return d;
}
__device__ __forceinline__ u64 fmul2(u64 a, u64 b) {
    u64 d;
    asm("mul.rn.f32x2 %0, %1, %2;" : "=l"(d) : "l"(a), "l"(b));
    return d;
}
__device__ __forceinline__ u64 pack2(float lo, float hi) {
    u64 d;
    asm("mov.b64 %0, {%1, %2};" : "=l"(d) : "f"(lo), "f"(hi));
    return d;
}
__device__ __forceinline__ float2 unpack2(u64 v) {
    float2 r;
    asm("mov.b64 {%0, %1}, %2;" : "=f"(r.x), "=f"(r.y) : "l"(v));
    return r;
}

// ---- tf32 mma.sync primitives (baseline PTX ISA, works on .target sm_103) -
__device__ __forceinline__ uint32_t f2tf32(float f) {
    uint32_t u;
    asm("cvt.rna.tf32.f32 %0, %1;" : "=r"(u) : "f"(f));
    return u;
}
// D(16x8,f32) += A(16x8,tf32,row) * B(8x8,tf32,col)
__device__ __forceinline__ void mma_tf32(float* c, const uint32_t* a,
                                         uint32_t b0, uint32_t b1) {
    asm volatile(
        "mma.sync.aligned.m16n8k8.row.col.f32.tf32.tf32.f32 "
        "{%0,%1,%2,%3}, {%4,%5,%6,%7}, {%8,%9}, {%0,%1,%2,%3};"
        : "+f"(c[0]), "+f"(c[1]), "+f"(c[2]), "+f"(c[3])
        : "r"(a[0]), "r"(a[1]), "r"(a[2]), "r"(a[3]), "r"(b0), "r"(b1));
}

// Scratch (no cudaMalloc allowed): qkv activations + attention output
__device__ float g_qkv[MROWS * QKVN];     // [B*S, 3*D]
__device__ float g_val[MROWS * DMODEL];   // [B*S, D]

// ---------------------------------------------------------------------------
// tf32 tensor-core GEMM (NT) via mma.sync: C[M,N] = A[M,K]*W[N,K]^T + bias[N]
// 128x128 tile, BK=16, 256 threads (8 warps, 4x2 -> warp tile 32x64).
// Smem row stride LDA=20 floats -> fragment LDS banks (20*lq+lr)%32 are all
// distinct within a warp quad pattern (conflict-free).
// ---------------------------------------------------------------------------
#define BM 128
#define BN 128
#define BK 16
#define LDA 20

__global__ __launch_bounds__(256)
void gemm_tf32_mma(const float* __restrict__ A,
                   const float* __restrict__ W,
                   const float* __restrict__ bias,
                   float* __restrict__ C,
                   int M, int N, int K)
{
    __shared__ __align__(16) uint32_t As[BM * LDA];   // [m][k] tf32
    __shared__ __align__(16) uint32_t Bs[BN * LDA];   // [n][k] tf32

    const int tid  = threadIdx.x;
    const int lane = tid & 31;
    const int wid  = tid >> 5;
    const int wm   = (wid & 3) * 32;    // warp M base within tile
    const int wn   = (wid >> 2) * 64;   // warp N base within tile
    const int lq   = lane >> 2;         // 0..7
    const int lr   = lane & 3;          // 0..3
    const int bm   = blockIdx.y * BM;
    const int bn   = blockIdx.x * BN;

    // staging map: 2 threads per row, 8 floats each
    const int srow = tid >> 1;          // 0..127
    const int skb  = (tid & 1) * 8;     // 0 or 8
    const float* ap = A + (size_t)(bm + srow) * K + skb;
    const float* bp = W + (size_t)(bn + srow) * K + skb;

    float4 ra0 = *(const float4*)(ap);
    float4 ra1 = *(const float4*)(ap + 4);
    float4 rb0 = *(const float4*)(bp);
    float4 rb1 = *(const float4*)(bp + 4);

    float acc[2][8][4];
    #pragma unroll
    for (int mt = 0; mt < 2; mt++)
        #pragma unroll
        for (int nt = 0; nt < 8; nt++)
            #pragma unroll
            for (int i = 0; i < 4; i++) acc[mt][nt][i] = 0.0f;

    for (int k0 = 0; k0 < K; k0 += BK) {
        __syncthreads();   // previous iteration's fragment reads complete
        {
            uint32_t* as = &As[srow * LDA + skb];
            as[0] = f2tf32(ra0.x); as[1] = f2tf32(ra0.y);
            as[2] = f2tf32(ra0.z); as[3] = f2tf32(ra0.w);
            as[4] = f2tf32(ra1.x); as[5] = f2tf32(ra1.y);
            as[6] = f2tf32(ra1.z); as[7] = f2tf32(ra1.w);
            uint32_t* bs = &Bs[srow * LDA + skb];
            bs[0] = f2tf32(rb0.x); bs[1] = f2tf32(rb0.y);
            bs[2] = f2tf32(rb0.z); bs[3] = f2tf32(rb0.w);
            bs[4] = f2tf32(rb1.x); bs[5] = f2tf32(rb1.y);
            bs[6] = f2tf32(rb1.z); bs[7] = f2tf32(rb1.w);
        }
        __syncthreads();

        if (k0 + BK < K) {   // prefetch next chunk; latency hides under MMAs
            ra0 = *(const float4*)(ap + k0 + BK);
            ra1 = *(const float4*)(ap + k0 + BK + 4);
            rb0 = *(const float4*)(bp + k0 + BK);
            rb1 = *(const float4*)(bp + k0 + BK + 4);
        }

        #pragma unroll
        for (int ks = 0; ks < 2; ks++) {
            const int kk = ks * 8;
            uint32_t af[2][4];
            #pragma unroll
            for (int mt = 0; mt < 2; mt++) {
                const uint32_t* s0 = &As[(wm + mt * 16 + lq) * LDA + kk];
                const uint32_t* s1 = s0 + 8 * LDA;
                af[mt][0] = s0[lr];     af[mt][2] = s0[lr + 4];
                af[mt][1] = s1[lr];     af[mt][3] = s1[lr + 4];
            }
            #pragma unroll
            for (int nt = 0; nt < 8; nt++) {
                const uint32_t* s = &Bs[(wn + nt * 8 + lq) * LDA + kk];
                const uint32_t b0 = s[lr];
                const uint32_t b1 = s[lr + 4];
                mma_tf32(acc[0][nt], af[0], b0, b1);
                mma_tf32(acc[1][nt], af[1], b0, b1);
            }
        }
    }

    // Epilogue: c0,c1 -> (row, 2lr..2lr+1), c2,c3 -> (row+8, same cols)
    #pragma unroll
    for (int mt = 0; mt < 2; mt++) {
        const int row = bm + wm + mt * 16 + lq;
        #pragma unroll
        for (int nt = 0; nt < 8; nt++) {
            const int col = bn + wn + nt * 8 + lr * 2;
            float2 bv = *(const float2*)(bias + col);
            float2 r0, r1;
            r0.x = acc[mt][nt][0] + bv.x;  r0.y = acc[mt][nt][1] + bv.y;
            r1.x = acc[mt][nt][2] + bv.x;  r1.y = acc[mt][nt][3] + bv.y;
            *(float2*)(C + (size_t)row * N + col)       = r0;
            *(float2*)(C + (size_t)(row + 8) * N + col) = r1;
        }
    }
}

// ---------------------------------------------------------------------------
// Flash attention (fp32, online softmax), packed f32x2 math. (validated R9)
// 2 threads per query row (headdim split 32/32, joined by shfl.xor 1).
// ---------------------------------------------------------------------------
#define BQ2 64
#define BKT 32
#define KROW 72   // padded floats per key row

__global__ __launch_bounds__(128)
void flash_attn_kernel()
{
    __shared__ __align__(16) float Ks[BKT * KROW];   // 9216 B
    __shared__ __align__(16) float Vs[BKT * KROW];   // 9216 B

    const int tid  = threadIdx.x;
    const int half = tid & 1;
    const int rloc = tid >> 1;
    const int bh   = blockIdx.y;
    const int b    = bh >> 4;
    const int h    = bh & 15;
    const int srow = blockIdx.x * BQ2 + rloc;

    const ulonglong2* qv = (const ulonglong2*)(g_qkv +
        (size_t)(b * SEQ + srow) * QKVN + h * 3 * HDIM + half * 32);
    u64 q2[16];
    #pragma unroll
    for (int i = 0; i < 8; i++) {
        ulonglong2 t = qv[i];
        q2[2 * i] = t.x; q2[2 * i + 1] = t.y;
    }

    u64 o2[16];
    #pragma unroll
    for (int i = 0; i < 16; i++) o2[i] = 0ULL;
    float mmax = -1e30f, l = 0.0f;
    const float rscale = 0.125f;

    const int lrow = tid >> 2;
    const int lf4  = (tid & 3) * 4;

    for (int kt = 0; kt < SEQ; kt += BKT) {
        __syncthreads();
        {
            const float4* kg = (const float4*)(g_qkv +
                (size_t)(b * SEQ + kt + lrow) * QKVN + h * 3 * HDIM + HDIM);
            const float4* vg = kg + (HDIM / 4);
            #pragma unroll
            for (int i = 0; i < 4; i++) {
                const int c4  = lf4 + i;
                const int dst = lrow * KROW + c4 * 4 + (c4 >= 8 ? 4 : 0);
                *(float4*)(Ks + dst) = kg[c4];
                *(float4*)(Vs + dst) = vg[c4];
            }
        }
        __syncthreads();

        float sc[BKT];
        float mnew = mmax;
        #pragma unroll
        for (int j = 0; j < BKT; j++) {
            const ulonglong2* kp = (const ulonglong2*)(Ks + j * KROW + half * 36);
            u64 sa = 0ULL, sb2 = 0ULL;
            #pragma unroll
            for (int i = 0; i < 8; i++) {
                ulonglong2 kv = kp[i];
                sa  = ffma2(q2[2 * i],     kv.x, sa);
                sb2 = ffma2(q2[2 * i + 1], kv.y, sb2);
            }
            float2 fa = unpack2(sa), fb = unpack2(sb2);
            float sp = (fa.x + fa.y) + (fb.x + fb.y);
            sp += __shfl_xor_sync(0xffffffffu, sp, 1);
            sp *= rscale;
            sc[j] = sp;
            mnew = fmaxf(mnew, sp);
        }

        const float corr = __expf(mmax - mnew);
        l *= corr;
        const u64 corr2 = pack2(corr, corr);
        #pragma unroll
        for (int i = 0; i < 16; i++) o2[i] = fmul2(o2[i], corr2);

        #pragma unroll
        for (int j = 0; j < BKT; j++) {
            const float p = __expf(sc[j] - mnew);
            l += p;
            const u64 p2 = pack2(p, p);
            const ulonglong2* vp = (const ulonglong2*)(Vs + j * KROW + half * 36);
            #pragma unroll
            for (int i = 0; i < 8; i++) {
                ulonglong2 vv = vp[i];
                o2[2 * i]     = ffma2(p2, vv.x, o2[2 * i]);
                o2[2 * i + 1] = ffma2(p2, vv.y, o2[2 * i + 1]);
            }
        }
        mmax = mnew;
    }

    const float inv = 1.0f / l;
    const u64 inv2 = pack2(inv, inv);
    ulonglong2* op = (ulonglong2*)(g_val +
        (size_t)(b * SEQ + srow) * DMODEL + h * HDIM + half * 32);
    #pragma unroll
    for (int i = 0; i < 8; i++) {
        ulonglong2 t;
        t.x = fmul2(o2[2 * i],     inv2);
        t.y = fmul2(o2[2 * i + 1], inv2);
        op[i] = t;
    }
}

// ---------------------------------------------------------------------------
// Launch: tf32-mma QKV GEMM -> flash attention -> tf32-mma output GEMM
// ---------------------------------------------------------------------------
extern "C" void kernel_launch(void* const* d_in, const int* in_sizes, int n_in,
                              void* d_out, int out_size)
{
    const float* x     = (const float*)d_in[0];   // [2,2048,1024]
    const float* w_qkv = (const float*)d_in[1];   // [3072,1024]
    const float* b_qkv = (const float*)d_in[2];   // [3072]
    const float* w_fc  = (const float*)d_in[3];   // [1024,1024]
    const float* b_fc  = (const float*)d_in[4];   // [1024]
    float* out = (float*)d_out;                   // [2,2048,1024]

    float* qkv_d = nullptr;
    float* val_d = nullptr;
    cudaGetSymbolAddress((void**)&qkv_d, g_qkv);
    cudaGetSymbolAddress((void**)&val_d, g_val);

    // 1) QKV projection: [4096,1024] x [3072,1024]^T + b -> [4096,3072]
    gemm_tf32_mma<<<dim3(QKVN / BN, MROWS / BM), 256>>>(
        x, w_qkv, b_qkv, qkv_d, MROWS, QKVN, DMODEL);

    // 2) Flash attention over all (b,h): writes g_val [4096,1024]
    flash_attn_kernel<<<dim3(SEQ / BQ2, BATCH * NHEAD), 128>>>();

    // 3) Output projection: [4096,1024] x [1024,1024]^T + b -> out
    gemm_tf32_mma<<<dim3(DMODEL / BN, MROWS / BM), 256>>>(
        val_d, w_fc, b_fc, out, MROWS, DMODEL, DMODEL);
}

// round 15
// speedup vs baseline: 2.8076x; 2.3032x over previous
#include <cuda_runtime.h>
#include <cstdint>

// Problem constants
#define BATCH   2
#define SEQ     2048
#define DMODEL  1024
#define NHEAD   16
#define HDIM    64
#define MROWS   (BATCH * SEQ)     // 4096
#define QKVN    (3 * DMODEL)      // 3072

typedef unsigned long long u64;

// ---- tf32 mma.sync primitives (baseline PTX ISA, works on .target sm_103) -
__device__ __forceinline__ uint32_t f2tf32(float f) {
    uint32_t u;
    asm("cvt.rna.tf32.f32 %0, %1;" : "=r"(u) : "f"(f));
    return u;
}
// D(16x8,f32) += A(16x8,tf32,row) * B(8x8,tf32,col)
// a0=A[lq][lr] a1=A[lq+8][lr] a2=A[lq][lr+4] a3=A[lq+8][lr+4]
// b0=B[k=lr][n=lq] b1=B[k=lr+4][n=lq]
// c0=C[lq][2lr] c1=C[lq][2lr+1] c2=C[lq+8][2lr] c3=C[lq+8][2lr+1]
__device__ __forceinline__ void mma_tf32(float* c, const uint32_t* a,
                                         uint32_t b0, uint32_t b1) {
    asm volatile(
        "mma.sync.aligned.m16n8k8.row.col.f32.tf32.tf32.f32 "
        "{%0,%1,%2,%3}, {%4,%5,%6,%7}, {%8,%9}, {%0,%1,%2,%3};"
        : "+f"(c[0]), "+f"(c[1]), "+f"(c[2]), "+f"(c[3])
        : "r"(a[0]), "r"(a[1]), "r"(a[2]), "r"(a[3]), "r"(b0), "r"(b1));
}

// Scratch (no cudaMalloc allowed): qkv activations + attention output
__device__ float g_qkv[MROWS * QKVN];     // [B*S, 3*D]
__device__ float g_val[MROWS * DMODEL];   // [B*S, D]

// ---------------------------------------------------------------------------
// tf32 tensor-core GEMM (NT) via mma.sync  (validated R13, unchanged)
// ---------------------------------------------------------------------------
#define BM 128
#define BN 128
#define BK 16
#define LDA 20

__global__ __launch_bounds__(256)
void gemm_tf32_mma(const float* __restrict__ A,
                   const float* __restrict__ W,
                   const float* __restrict__ bias,
                   float* __restrict__ C,
                   int M, int N, int K)
{
    __shared__ __align__(16) uint32_t As[BM * LDA];   // [m][k] tf32
    __shared__ __align__(16) uint32_t Bs[BN * LDA];   // [n][k] tf32

    const int tid  = threadIdx.x;
    const int lane = tid & 31;
    const int wid  = tid >> 5;
    const int wm   = (wid & 3) * 32;
    const int wn   = (wid >> 2) * 64;
    const int lq   = lane >> 2;
    const int lr   = lane & 3;
    const int bm   = blockIdx.y * BM;
    const int bn   = blockIdx.x * BN;

    const int srow = tid >> 1;
    const int skb  = (tid & 1) * 8;
    const float* ap = A + (size_t)(bm + srow) * K + skb;
    const float* bp = W + (size_t)(bn + srow) * K + skb;

    float4 ra0 = *(const float4*)(ap);
    float4 ra1 = *(const float4*)(ap + 4);
    float4 rb0 = *(const float4*)(bp);
    float4 rb1 = *(const float4*)(bp + 4);

    float acc[2][8][4];
    #pragma unroll
    for (int mt = 0; mt < 2; mt++)
        #pragma unroll
        for (int nt = 0; nt < 8; nt++)
            #pragma unroll
            for (int i = 0; i < 4; i++) acc[mt][nt][i] = 0.0f;

    for (int k0 = 0; k0 < K; k0 += BK) {
        __syncthreads();
        {
            uint32_t* as = &As[srow * LDA + skb];
            as[0] = f2tf32(ra0.x); as[1] = f2tf32(ra0.y);
            as[2] = f2tf32(ra0.z); as[3] = f2tf32(ra0.w);
            as[4] = f2tf32(ra1.x); as[5] = f2tf32(ra1.y);
            as[6] = f2tf32(ra1.z); as[7] = f2tf32(ra1.w);
            uint32_t* bs = &Bs[srow * LDA + skb];
            bs[0] = f2tf32(rb0.x); bs[1] = f2tf32(rb0.y);
            bs[2] = f2tf32(rb0.z); bs[3] = f2tf32(rb0.w);
            bs[4] = f2tf32(rb1.x); bs[5] = f2tf32(rb1.y);
            bs[6] = f2tf32(rb1.z); bs[7] = f2tf32(rb1.w);
        }
        __syncthreads();

        if (k0 + BK < K) {
            ra0 = *(const float4*)(ap + k0 + BK);
            ra1 = *(const float4*)(ap + k0 + BK + 4);
            rb0 = *(const float4*)(bp + k0 + BK);
            rb1 = *(const float4*)(bp + k0 + BK + 4);
        }

        #pragma unroll
        for (int ks = 0; ks < 2; ks++) {
            const int kk = ks * 8;
            uint32_t af[2][4];
            #pragma unroll
            for (int mt = 0; mt < 2; mt++) {
                const uint32_t* s0 = &As[(wm + mt * 16 + lq) * LDA + kk];
                const uint32_t* s1 = s0 + 8 * LDA;
                af[mt][0] = s0[lr];     af[mt][2] = s0[lr + 4];
                af[mt][1] = s1[lr];     af[mt][3] = s1[lr + 4];
            }
            #pragma unroll
            for (int nt = 0; nt < 8; nt++) {
                const uint32_t* s = &Bs[(wn + nt * 8 + lq) * LDA + kk];
                const uint32_t b0 = s[lr];
                const uint32_t b1 = s[lr + 4];
                mma_tf32(acc[0][nt], af[0], b0, b1);
                mma_tf32(acc[1][nt], af[1], b0, b1);
            }
        }
    }

    #pragma unroll
    for (int mt = 0; mt < 2; mt++) {
        const int row = bm + wm + mt * 16 + lq;
        #pragma unroll
        for (int nt = 0; nt < 8; nt++) {
            const int col = bn + wn + nt * 8 + lr * 2;
            float2 bv = *(const float2*)(bias + col);
            float2 r0, r1;
            r0.x = acc[mt][nt][0] + bv.x;  r0.y = acc[mt][nt][1] + bv.y;
            r1.x = acc[mt][nt][2] + bv.x;  r1.y = acc[mt][nt][3] + bv.y;
            *(float2*)(C + (size_t)row * N + col)       = r0;
            *(float2*)(C + (size_t)(row + 8) * N + col) = r1;
        }
    }
}

// ---------------------------------------------------------------------------
// Flash attention via tf32 mma.sync.
// CTA = 256 threads (8 warps) = 128 query rows of one (b,h); key tiles of 32.
// FIX vs R14: K/V rows are 64 elements wide -> they need their own strides
// (FKLD/FVLD >= 64+pad). R14 used 36 for all three arrays, overlapping rows
// and writing out of bounds.
//   FKLD=68: QK B-frag banks (4lq+lr)%32  -> conflict-free
//   FVLD=72: PV B-frag banks (8lr+lq)%32  -> conflict-free
//   FPLD=36: PV A-frag banks (4lq+lr)%32  -> conflict-free
// ---------------------------------------------------------------------------
#define FBQ  128   // query rows per CTA
#define FBK  32    // keys per tile
#define FKLD 68    // K smem row stride (uint32)
#define FVLD 72    // V smem row stride (uint32)
#define FPLD 36    // P smem row stride (uint32)

__global__ __launch_bounds__(256)
void flash_attn_mma()
{
    __shared__ __align__(16) uint32_t Ks[FBK * FKLD];   // [key][d]    8704 B
    __shared__ __align__(16) uint32_t Vs[FBK * FVLD];   // [key][d]    9216 B
    __shared__ __align__(16) uint32_t Ps[FBQ * FPLD];   // [qrow][key] 18432 B

    const int tid  = threadIdx.x;
    const int lane = tid & 31;
    const int wid  = tid >> 5;         // 0..7
    const int lq   = lane >> 2;        // 0..7
    const int lr   = lane & 3;         // 0..3
    const int bh   = blockIdx.y;
    const int b    = bh >> 4;
    const int h    = bh & 15;
    const int q0   = blockIdx.x * FBQ;
    const int wrow = wid * 16;

    // ---- Q fragments (once): rows q0+wrow+{lq, lq+8}, all 64 dims ----
    const float* qbase = g_qkv + (size_t)(b * SEQ + q0 + wrow) * QKVN + h * 3 * HDIM;
    uint32_t qf[8][4];
    #pragma unroll
    for (int kk = 0; kk < 8; kk++) {
        qf[kk][0] = f2tf32(qbase[(size_t)lq * QKVN       + kk * 8 + lr]);
        qf[kk][1] = f2tf32(qbase[(size_t)(lq + 8) * QKVN + kk * 8 + lr]);
        qf[kk][2] = f2tf32(qbase[(size_t)lq * QKVN       + kk * 8 + lr + 4]);
        qf[kk][3] = f2tf32(qbase[(size_t)(lq + 8) * QKVN + kk * 8 + lr + 4]);
    }

    float o[8][4];
    #pragma unroll
    for (int nt = 0; nt < 8; nt++)
        #pragma unroll
        for (int i = 0; i < 4; i++) o[nt][i] = 0.0f;
    float m0 = -1e30f, m1 = -1e30f, l0 = 0.0f, l1 = 0.0f;

    // tile loader map: 8 threads per key row, each 8 floats (2 float4)
    const int lrow = tid >> 3;          // 0..31
    const int lseg = (tid & 7) * 8;     // 0,8,...,56

    for (int kt = 0; kt < SEQ; kt += FBK) {
        __syncthreads();    // previous tile's K/V reads complete
        {
            const float* kg = g_qkv + (size_t)(b * SEQ + kt + lrow) * QKVN
                            + h * 3 * HDIM + HDIM + lseg;
            const float* vg = kg + HDIM;
            float4 k0 = *(const float4*)(kg);
            float4 k1 = *(const float4*)(kg + 4);
            float4 v0 = *(const float4*)(vg);
            float4 v1 = *(const float4*)(vg + 4);
            uint32_t* kd = &Ks[lrow * FKLD + lseg];
            kd[0] = f2tf32(k0.x); kd[1] = f2tf32(k0.y);
            kd[2] = f2tf32(k0.z); kd[3] = f2tf32(k0.w);
            kd[4] = f2tf32(k1.x); kd[5] = f2tf32(k1.y);
            kd[6] = f2tf32(k1.z); kd[7] = f2tf32(k1.w);
            uint32_t* vd = &Vs[lrow * FVLD + lseg];
            vd[0] = f2tf32(v0.x); vd[1] = f2tf32(v0.y);
            vd[2] = f2tf32(v0.z); vd[3] = f2tf32(v0.w);
            vd[4] = f2tf32(v1.x); vd[5] = f2tf32(v1.y);
            vd[6] = f2tf32(v1.z); vd[7] = f2tf32(v1.w);
        }
        __syncthreads();

        // ---- S = Q K^T : per warp 16x32 in 4 n-tiles ----
        float s[4][4];
        #pragma unroll
        for (int nt = 0; nt < 4; nt++)
            #pragma unroll
            for (int i = 0; i < 4; i++) s[nt][i] = 0.0f;

        #pragma unroll
        for (int kk = 0; kk < 8; kk++) {
            #pragma unroll
            for (int nt = 0; nt < 4; nt++) {
                const uint32_t* kp = &Ks[(nt * 8 + lq) * FKLD + kk * 8];
                mma_tf32(s[nt], qf[kk], kp[lr], kp[lr + 4]);
            }
        }

        // scale 1/sqrt(64) and row max (row spans the 4-lane quad)
        float rm0 = -1e30f, rm1 = -1e30f;
        #pragma unroll
        for (int nt = 0; nt < 4; nt++) {
            #pragma unroll
            for (int i = 0; i < 4; i++) s[nt][i] *= 0.125f;
            rm0 = fmaxf(rm0, fmaxf(s[nt][0], s[nt][1]));
            rm1 = fmaxf(rm1, fmaxf(s[nt][2], s[nt][3]));
        }
        rm0 = fmaxf(rm0, __shfl_xor_sync(0xffffffffu, rm0, 1));
        rm0 = fmaxf(rm0, __shfl_xor_sync(0xffffffffu, rm0, 2));
        rm1 = fmaxf(rm1, __shfl_xor_sync(0xffffffffu, rm1, 1));
        rm1 = fmaxf(rm1, __shfl_xor_sync(0xffffffffu, rm1, 2));

        const float mn0 = fmaxf(m0, rm0);
        const float mn1 = fmaxf(m1, rm1);
        const float c0  = __expf(m0 - mn0);
        const float c1  = __expf(m1 - mn1);

        // exponentiate, write P (tf32) to warp-private strip, row partial sums
        float ps0 = 0.0f, ps1 = 0.0f;
        #pragma unroll
        for (int nt = 0; nt < 4; nt++) {
            const float p0 = __expf(s[nt][0] - mn0);
            const float p1 = __expf(s[nt][1] - mn0);
            const float p2 = __expf(s[nt][2] - mn1);
            const float p3 = __expf(s[nt][3] - mn1);
            ps0 += p0 + p1;
            ps1 += p2 + p3;
            uint32_t* pr0 = &Ps[(wrow + lq) * FPLD + nt * 8 + 2 * lr];
            pr0[0] = f2tf32(p0);  pr0[1] = f2tf32(p1);
            uint32_t* pr1 = pr0 + 8 * FPLD;
            pr1[0] = f2tf32(p2);  pr1[1] = f2tf32(p3);
        }
        ps0 += __shfl_xor_sync(0xffffffffu, ps0, 1);
        ps0 += __shfl_xor_sync(0xffffffffu, ps0, 2);
        ps1 += __shfl_xor_sync(0xffffffffu, ps1, 1);
        ps1 += __shfl_xor_sync(0xffffffffu, ps1, 2);
        l0 = l0 * c0 + ps0;
        l1 = l1 * c1 + ps1;
        m0 = mn0;  m1 = mn1;

        // rescale output accumulators
        #pragma unroll
        for (int nt = 0; nt < 8; nt++) {
            o[nt][0] *= c0;  o[nt][1] *= c0;
            o[nt][2] *= c1;  o[nt][3] *= c1;
        }

        __syncwarp();   // P stores visible to this warp's fragment loads

        // ---- O += P V : 4 key k-tiles x 8 d n-tiles ----
        #pragma unroll
        for (int kk = 0; kk < 4; kk++) {
            uint32_t a[4];
            const uint32_t* p0 = &Ps[(wrow + lq) * FPLD + kk * 8];
            const uint32_t* p1 = p0 + 8 * FPLD;
            a[0] = p0[lr];      a[2] = p0[lr + 4];
            a[1] = p1[lr];      a[3] = p1[lr + 4];
            #pragma unroll
            for (int nt = 0; nt < 8; nt++) {
                const uint32_t* vp = &Vs[(kk * 8 + lr) * FVLD + nt * 8 + lq];
                mma_tf32(o[nt], a, vp[0], vp[4 * FVLD]);
            }
        }
        __syncwarp();   // PV fragment loads done before next tile's P stores
    }

    // epilogue: normalize and write g_val rows (q0+wrow+lq, +8)
    const float inv0 = 1.0f / l0;
    const float inv1 = 1.0f / l1;
    const size_t row0 = (size_t)(b * SEQ + q0 + wrow + lq);
    #pragma unroll
    for (int nt = 0; nt < 8; nt++) {
        const int col = h * HDIM + nt * 8 + 2 * lr;
        float2 r0, r1;
        r0.x = o[nt][0] * inv0;  r0.y = o[nt][1] * inv0;
        r1.x = o[nt][2] * inv1;  r1.y = o[nt][3] * inv1;
        *(float2*)(g_val + row0 * DMODEL + col)       = r0;
        *(float2*)(g_val + (row0 + 8) * DMODEL + col) = r1;
    }
}

// ---------------------------------------------------------------------------
// Launch: tf32-mma QKV GEMM -> tf32-mma flash attention -> tf32-mma out GEMM
// ---------------------------------------------------------------------------
extern "C" void kernel_launch(void* const* d_in, const int* in_sizes, int n_in,
                              void* d_out, int out_size)
{
    const float* x     = (const float*)d_in[0];   // [2,2048,1024]
    const float* w_qkv = (const float*)d_in[1];   // [3072,1024]
    const float* b_qkv = (const float*)d_in[2];   // [3072]
    const float* w_fc  = (const float*)d_in[3];   // [1024,1024]
    const float* b_fc  = (const float*)d_in[4];   // [1024]
    float* out = (float*)d_out;                   // [2,2048,1024]

    float* qkv_d = nullptr;
    float* val_d = nullptr;
    cudaGetSymbolAddress((void**)&qkv_d, g_qkv);
    cudaGetSymbolAddress((void**)&val_d, g_val);

    // 1) QKV projection: [4096,1024] x [3072,1024]^T + b -> [4096,3072]
    gemm_tf32_mma<<<dim3(QKVN / BN, MROWS / BM), 256>>>(
        x, w_qkv, b_qkv, qkv_d, MROWS, QKVN, DMODEL);

    // 2) Flash attention (tensor-core): writes g_val [4096,1024]
    flash_attn_mma<<<dim3(SEQ / FBQ, BATCH * NHEAD), 256>>>();

    // 3) Output projection: [4096,1024] x [1024,1024]^T + b -> out
    gemm_tf32_mma<<<dim3(DMODEL / BN, MROWS / BM), 256>>>(
        val_d, w_fc, b_fc, out, MROWS, DMODEL, DMODEL);
}

// round 17
// speedup vs baseline: 2.8939x; 1.0307x over previous
#include <cuda_runtime.h>
#include <cstdint>

// Problem constants
#define BATCH   2
#define SEQ     2048
#define DMODEL  1024
#define NHEAD   16
#define HDIM    64
#define MROWS   (BATCH * SEQ)     // 4096
#define QKVN    (3 * DMODEL)      // 3072

// ---- tf32 mma.sync primitives (baseline PTX ISA, works on .target sm_103) -
__device__ __forceinline__ uint32_t f2tf32(float f) {
    uint32_t u;
    asm("cvt.rna.tf32.f32 %0, %1;" : "=r"(u) : "f"(f));
    return u;
}
// D(16x8,f32) += A(16x8,tf32,row) * B(8x8,tf32,col)
// a0=A[lq][lr] a1=A[lq+8][lr] a2=A[lq][lr+4] a3=A[lq+8][lr+4]
// b0=B[k=lr][n=lq] b1=B[k=lr+4][n=lq]
// c0=C[lq][2lr] c1=C[lq][2lr+1] c2=C[lq+8][2lr] c3=C[lq+8][2lr+1]
__device__ __forceinline__ void mma_tf32(float* c, const uint32_t* a,
                                         uint32_t b0, uint32_t b1) {
    asm volatile(
        "mma.sync.aligned.m16n8k8.row.col.f32.tf32.tf32.f32 "
        "{%0,%1,%2,%3}, {%4,%5,%6,%7}, {%8,%9}, {%0,%1,%2,%3};"
        : "+f"(c[0]), "+f"(c[1]), "+f"(c[2]), "+f"(c[3])
        : "r"(a[0]), "r"(a[1]), "r"(a[2]), "r"(a[3]), "r"(b0), "r"(b1));
}
__device__ __forceinline__ uint32_t smem_u32(const void* p) {
    uint32_t a;
    asm("{ .reg .u64 t; cvta.to.shared.u64 t, %1; cvt.u32.u64 %0, t; }"
        : "=r"(a) : "l"(p));
    return a;
}
__device__ __forceinline__ void cp_async16(uint32_t dst, const void* src) {
    asm volatile("cp.async.cg.shared.global [%0], [%1], 16;"
                 :: "r"(dst), "l"(src) : "memory");
}
#define CP_COMMIT() asm volatile("cp.async.commit_group;" ::: "memory")
#define CP_WAIT(n)  asm volatile("cp.async.wait_group %0;" :: "n"(n) : "memory")

// Scratch (no cudaMalloc allowed)
__device__ float g_qkv[MROWS * QKVN];      // [B*S, 3*D] activations
__device__ float g_val[MROWS * DMODEL];    // [B*S, D] attention out (tf32-rounded)
__device__ float g_x[MROWS * DMODEL];      // tf32-rounded x
__device__ float g_wqkv[QKVN * DMODEL];    // tf32-rounded w_qkv
__device__ float g_wfc[DMODEL * DMODEL];   // tf32-rounded w_fc

// ---------------------------------------------------------------------------
// Prepass: round fp32 -> tf32-exact fp32 (so GEMM MMA truncation is exact)
// ---------------------------------------------------------------------------
__global__ __launch_bounds__(256)
void round_tf32(const float* __restrict__ src, float* __restrict__ dst, int n)
{
    const int i = (blockIdx.x * 256 + threadIdx.x) * 4;
    if (i < n) {
        float4 v = *(const float4*)(src + i);
        float4 r;
        r.x = __uint_as_float(f2tf32(v.x));
        r.y = __uint_as_float(f2tf32(v.y));
        r.z = __uint_as_float(f2tf32(v.z));
        r.w = __uint_as_float(f2tf32(v.w));
        *(float4*)(dst + i) = r;
    }
}

// ---------------------------------------------------------------------------
// tf32 tensor-core GEMM (NT), cp.async double-buffered mainloop.
// C[M,N] = A[M,K]*W[N,K]^T + bias[N].  A and W must be tf32-rounded fp32.
// 128x128 tile, BK=32 (LDA=36 pad -> fragment banks (4lq+lr) conflict-free),
// 2 smem stages, 1 cp.async group in flight, 2 barriers per 32-wide K chunk.
// ---------------------------------------------------------------------------
#define BM 128
#define BN 128
#define GBK 32
#define GLD 36
#define STG_W (128 * GLD)                 // uint32 words per operand stage (4608)
#define STAGE_W (2 * STG_W)               // words per stage (A+B) = 9216
#define SMEM_GEMM_BYTES (2 * STAGE_W * 4) // 73728

__global__ __launch_bounds__(256)
void gemm_tf32_mma(const float* __restrict__ A,
                   const float* __restrict__ W,
                   const float* __restrict__ bias,
                   float* __restrict__ C,
                   int M, int N, int K)
{
    extern __shared__ __align__(16) uint32_t dsm[];

    const int tid  = threadIdx.x;
    const int lane = tid & 31;
    const int wid  = tid >> 5;
    const int wm   = (wid & 3) * 32;
    const int wn   = (wid >> 2) * 64;
    const int lq   = lane >> 2;
    const int lr   = lane & 3;
    const int bm   = blockIdx.y * BM;
    const int bn   = blockIdx.x * BN;

    // cp.async map: 2 threads per row, 4 x 16B each (row halves 0..15 / 16..31)
    const int crow = tid >> 1;           // 0..127
    const int ccol = (tid & 1) * 16;     // float offset 0 or 16
    const float* aG = A + (size_t)(bm + crow) * K + ccol;
    const float* bG = W + (size_t)(bn + crow) * K + ccol;
    const uint32_t sm0 = smem_u32(dsm);
    const uint32_t aSoff = (uint32_t)(crow * GLD + ccol) * 4;

    auto prefetch = [&](int c, int stg) {
        const uint32_t abase = sm0 + stg * (STAGE_W * 4) + aSoff;
        const uint32_t bbase = abase + STG_W * 4;
        const float* ag = aG + c * GBK;
        const float* bg = bG + c * GBK;
        #pragma unroll
        for (int i = 0; i < 4; i++) {
            cp_async16(abase + i * 16, ag + i * 4);
            cp_async16(bbase + i * 16, bg + i * 4);
        }
    };

    float acc[2][8][4];
    #pragma unroll
    for (int mt = 0; mt < 2; mt++)
        #pragma unroll
        for (int nt = 0; nt < 8; nt++)
            #pragma unroll
            for (int i = 0; i < 4; i++) acc[mt][nt][i] = 0.0f;

    const int NCH = K / GBK;    // 32
    prefetch(0, 0);
    CP_COMMIT();

    for (int c = 0; c < NCH; c++) {
        const int s = c & 1;
        if (c + 1 < NCH) {      // stage s^1 last read in iter c-1 (bottom sync)
            prefetch(c + 1, s ^ 1);
            CP_COMMIT();
            CP_WAIT(1);         // chunk c landed (FIFO)
        } else {
            CP_WAIT(0);
        }
        __syncthreads();

        const uint32_t* As = dsm + s * STAGE_W;
        const uint32_t* Bs = As + STG_W;

        #pragma unroll
        for (int ks = 0; ks < 4; ks++) {
            const int kk = ks * 8;
            uint32_t af[2][4];
            #pragma unroll
            for (int mt = 0; mt < 2; mt++) {
                const uint32_t* s0 = &As[(wm + mt * 16 + lq) * GLD + kk];
                const uint32_t* s1 = s0 + 8 * GLD;
                af[mt][0] = s0[lr];     af[mt][2] = s0[lr + 4];
                af[mt][1] = s1[lr];     af[mt][3] = s1[lr + 4];
            }
            #pragma unroll
            for (int nt = 0; nt < 8; nt++) {
                const uint32_t* sp = &Bs[(wn + nt * 8 + lq) * GLD + kk];
                const uint32_t b0 = sp[lr];
                const uint32_t b1 = sp[lr + 4];
                mma_tf32(acc[0][nt], af[0], b0, b1);
                mma_tf32(acc[1][nt], af[1], b0, b1);
            }
        }
        __syncthreads();        // reads done before next iter overwrites s^1
    }

    #pragma unroll
    for (int mt = 0; mt < 2; mt++) {
        const int row = bm + wm + mt * 16 + lq;
        #pragma unroll
        for (int nt = 0; nt < 8; nt++) {
            const int col = bn + wn + nt * 8 + lr * 2;
            float2 bv = *(const float2*)(bias + col);
            float2 r0, r1;
            r0.x = acc[mt][nt][0] + bv.x;  r0.y = acc[mt][nt][1] + bv.y;
            r1.x = acc[mt][nt][2] + bv.x;  r1.y = acc[mt][nt][3] + bv.y;
            *(float2*)(C + (size_t)row * N + col)       = r0;
            *(float2*)(C + (size_t)(row + 8) * N + col) = r1;
        }
    }
}

// ---------------------------------------------------------------------------
// Flash attention via tf32 mma.sync (validated R15; epilogue rounds to
// tf32 so GEMM2 can consume g_val without conversion).
//   FKLD=68: QK B-frag banks (4lq+lr)%32  -> conflict-free
//   FVLD=72: PV B-frag banks (8lr+lq)%32  -> conflict-free
//   FPLD=36: PV A-frag banks (4lq+lr)%32  -> conflict-free
// ---------------------------------------------------------------------------
#define FBQ  128
#define FBK  32
#define FKLD 68
#define FVLD 72
#define FPLD 36

__global__ __launch_bounds__(256)
void flash_attn_mma()
{
    __shared__ __align__(16) uint32_t Ks[FBK * FKLD];
    __shared__ __align__(16) uint32_t Vs[FBK * FVLD];
    __shared__ __align__(16) uint32_t Ps[FBQ * FPLD];

    const int tid  = threadIdx.x;
    const int lane = tid & 31;
    const int wid  = tid >> 5;
    const int lq   = lane >> 2;
    const int lr   = lane & 3;
    const int bh   = blockIdx.y;
    const int b    = bh >> 4;
    const int h    = bh & 15;
    const int q0   = blockIdx.x * FBQ;
    const int wrow = wid * 16;

    const float* qbase = g_qkv + (size_t)(b * SEQ + q0 + wrow) * QKVN + h * 3 * HDIM;
    uint32_t qf[8][4];
    #pragma unroll
    for (int kk = 0; kk < 8; kk++) {
        qf[kk][0] = f2tf32(qbase[(size_t)lq * QKVN       + kk * 8 + lr]);
        qf[kk][1] = f2tf32(qbase[(size_t)(lq + 8) * QKVN + kk * 8 + lr]);
        qf[kk][2] = f2tf32(qbase[(size_t)lq * QKVN       + kk * 8 + lr + 4]);
        qf[kk][3] = f2tf32(qbase[(size_t)(lq + 8) * QKVN + kk * 8 + lr + 4]);
    }

    float o[8][4];
    #pragma unroll
    for (int nt = 0; nt < 8; nt++)
        #pragma unroll
        for (int i = 0; i < 4; i++) o[nt][i] = 0.0f;
    float m0 = -1e30f, m1 = -1e30f, l0 = 0.0f, l1 = 0.0f;

    const int lrow = tid >> 3;
    const int lseg = (tid & 7) * 8;

    for (int kt = 0; kt < SEQ; kt += FBK) {
        __syncthreads();
        {
            const float* kg = g_qkv + (size_t)(b * SEQ + kt + lrow) * QKVN
                            + h * 3 * HDIM + HDIM + lseg;
            const float* vg = kg + HDIM;
            float4 k0 = *(const float4*)(kg);
            float4 k1 = *(const float4*)(kg + 4);
            float4 v0 = *(const float4*)(vg);
            float4 v1 = *(const float4*)(vg + 4);
            uint32_t* kd = &Ks[lrow * FKLD + lseg];
            kd[0] = f2tf32(k0.x); kd[1] = f2tf32(k0.y);
            kd[2] = f2tf32(k0.z); kd[3] = f2tf32(k0.w);
            kd[4] = f2tf32(k1.x); kd[5] = f2tf32(k1.y);
            kd[6] = f2tf32(k1.z); kd[7] = f2tf32(k1.w);
            uint32_t* vd = &Vs[lrow * FVLD + lseg];
            vd[0] = f2tf32(v0.x); vd[1] = f2tf32(v0.y);
            vd[2] = f2tf32(v0.z); vd[3] = f2tf32(v0.w);
            vd[4] = f2tf32(v1.x); vd[5] = f2tf32(v1.y);
            vd[6] = f2tf32(v1.z); vd[7] = f2tf32(v1.w);
        }
        __syncthreads();

        float s[4][4];
        #pragma unroll
        for (int nt = 0; nt < 4; nt++)
            #pragma unroll
            for (int i = 0; i < 4; i++) s[nt][i] = 0.0f;

        #pragma unroll
        for (int kk = 0; kk < 8; kk++) {
            #pragma unroll
            for (int nt = 0; nt < 4; nt++) {
                const uint32_t* kp = &Ks[(nt * 8 + lq) * FKLD + kk * 8];
                mma_tf32(s[nt], qf[kk], kp[lr], kp[lr + 4]);
            }
        }

        float rm0 = -1e30f, rm1 = -1e30f;
        #pragma unroll
        for (int nt = 0; nt < 4; nt++) {
            #pragma unroll
            for (int i = 0; i < 4; i++) s[nt][i] *= 0.125f;
            rm0 = fmaxf(rm0, fmaxf(s[nt][0], s[nt][1]));
            rm1 = fmaxf(rm1, fmaxf(s[nt][2], s[nt][3]));
        }
        rm0 = fmaxf(rm0, __shfl_xor_sync(0xffffffffu, rm0, 1));
        rm0 = fmaxf(rm0, __shfl_xor_sync(0xffffffffu, rm0, 2));
        rm1 = fmaxf(rm1, __shfl_xor_sync(0xffffffffu, rm1, 1));
        rm1 = fmaxf(rm1, __shfl_xor_sync(0xffffffffu, rm1, 2));

        const float mn0 = fmaxf(m0, rm0);
        const float mn1 = fmaxf(m1, rm1);
        const float c0  = __expf(m0 - mn0);
        const float c1  = __expf(m1 - mn1);

        float ps0 = 0.0f, ps1 = 0.0f;
        #pragma unroll
        for (int nt = 0; nt < 4; nt++) {
            const float p0 = __expf(s[nt][0] - mn0);
            const float p1 = __expf(s[nt][1] - mn0);
            const float p2 = __expf(s[nt][2] - mn1);
            const float p3 = __expf(s[nt][3] - mn1);
            ps0 += p0 + p1;
            ps1 += p2 + p3;
            uint32_t* pr0 = &Ps[(wrow + lq) * FPLD + nt * 8 + 2 * lr];
            pr0[0] = f2tf32(p0);  pr0[1] = f2tf32(p1);
            uint32_t* pr1 = pr0 + 8 * FPLD;
            pr1[0] = f2tf32(p2);  pr1[1] = f2tf32(p3);
        }
        ps0 += __shfl_xor_sync(0xffffffffu, ps0, 1);
        ps0 += __shfl_xor_sync(0xffffffffu, ps0, 2);
        ps1 += __shfl_xor_sync(0xffffffffu, ps1, 1);
        ps1 += __shfl_xor_sync(0xffffffffu, ps1, 2);
        l0 = l0 * c0 + ps0;
        l1 = l1 * c1 + ps1;
        m0 = mn0;  m1 = mn1;

        #pragma unroll
        for (int nt = 0; nt < 8; nt++) {
            o[nt][0] *= c0;  o[nt][1] *= c0;
            o[nt][2] *= c1;  o[nt][3] *= c1;
        }

        __syncwarp();

        #pragma unroll
        for (int kk = 0; kk < 4; kk++) {
            uint32_t a[4];
            const uint32_t* p0 = &Ps[(wrow + lq) * FPLD + kk * 8];
            const uint32_t* p1 = p0 + 8 * FPLD;
            a[0] = p0[lr];      a[2] = p0[lr + 4];
            a[1] = p1[lr];      a[3] = p1[lr + 4];
            #pragma unroll
            for (int nt = 0; nt < 8; nt++) {
                const uint32_t* vp = &Vs[(kk * 8 + lr) * FVLD + nt * 8 + lq];
                mma_tf32(o[nt], a, vp[0], vp[4 * FVLD]);
            }
        }
        __syncwarp();
    }

    // epilogue: normalize, round to tf32 (GEMM2 consumes raw bits), store
    const float inv0 = 1.0f / l0;
    const float inv1 = 1.0f / l1;
    const size_t row0 = (size_t)(b * SEQ + q0 + wrow + lq);
    #pragma unroll
    for (int nt = 0; nt < 8; nt++) {
        const int col = h * HDIM + nt * 8 + 2 * lr;
        float2 r0, r1;
        r0.x = __uint_as_float(f2tf32(o[nt][0] * inv0));
        r0.y = __uint_as_float(f2tf32(o[nt][1] * inv0));
        r1.x = __uint_as_float(f2tf32(o[nt][2] * inv1));
        r1.y = __uint_as_float(f2tf32(o[nt][3] * inv1));
        *(float2*)(g_val + row0 * DMODEL + col)       = r0;
        *(float2*)(g_val + (row0 + 8) * DMODEL + col) = r1;
    }
}

// ---------------------------------------------------------------------------
// Launch: tf32 prepass -> QKV GEMM -> flash attention -> output GEMM
// ---------------------------------------------------------------------------
extern "C" void kernel_launch(void* const* d_in, const int* in_sizes, int n_in,
                              void* d_out, int out_size)
{
    const float* x     = (const float*)d_in[0];   // [2,2048,1024]
    const float* w_qkv = (const float*)d_in[1];   // [3072,1024]
    const float* b_qkv = (const float*)d_in[2];   // [3072]
    const float* w_fc  = (const float*)d_in[3];   // [1024,1024]
    const float* b_fc  = (const float*)d_in[4];   // [1024]
    float* out = (float*)d_out;                   // [2,2048,1024]

    float *qkv_d, *val_d, *x_d, *wqkv_d, *wfc_d;
    cudaGetSymbolAddress((void**)&qkv_d,  g_qkv);
    cudaGetSymbolAddress((void**)&val_d,  g_val);
    cudaGetSymbolAddress((void**)&x_d,    g_x);
    cudaGetSymbolAddress((void**)&wqkv_d, g_wqkv);
    cudaGetSymbolAddress((void**)&wfc_d,  g_wfc);

    cudaFuncSetAttribute(gemm_tf32_mma,
                         cudaFuncAttributeMaxDynamicSharedMemorySize,
                         SMEM_GEMM_BYTES);

    // 0) Round inputs to tf32-exact fp32 (GEMM cp.async path needs no cvt)
    round_tf32<<<(MROWS * DMODEL / 4 + 255) / 256, 256>>>(x, x_d, MROWS * DMODEL);
    round_tf32<<<(QKVN * DMODEL / 4 + 255) / 256, 256>>>(w_qkv, wqkv_d, QKVN * DMODEL);
    round_tf32<<<(DMODEL * DMODEL / 4 + 255) / 256, 256>>>(w_fc, wfc_d, DMODEL * DMODEL);

    // 1) QKV projection: [4096,1024] x [3072,1024]^T + b -> [4096,3072]
    gemm_tf32_mma<<<dim3(QKVN / BN, MROWS / BM), 256, SMEM_GEMM_BYTES>>>(
        x_d, wqkv_d, b_qkv, qkv_d, MROWS, QKVN, DMODEL);

    // 2) Flash attention (tensor-core): writes tf32-rounded g_val [4096,1024]
    flash_attn_mma<<<dim3(SEQ / FBQ, BATCH * NHEAD), 256>>>();

    // 3) Output projection: [4096,1024] x [1024,1024]^T + b -> out
    gemm_tf32_mma<<<dim3(DMODEL / BN, MROWS / BM), 256, SMEM_GEMM_BYTES>>>(
        val_d, wfc_d, b_fc, out, MROWS, DMODEL, DMODEL);
}